// round 1
// baseline (speedup 1.0000x reference)
#include <cuda_runtime.h>
#include <cuda_bf16.h>
#include <cstdint>

// ---------------------------------------------------------------------------
// SelfAttention: B=8, N=2048, D=1024, ATT=128
//   f = x@Wf + bf ; g = x@Wg + bg
//   att = softmax(f @ g^T)            (per batch, row softmax over 2048)
//   out = att @ x + x
//
// Accuracy strategy: every GEMM runs on bf16 tensor cores with hi/lo splitting
// (3 products: hi*hi + hi*lo + lo*hi), giving ~fp32 accuracy (~1e-5 rel).
// ---------------------------------------------------------------------------

#define BATCH 8
#define SEQ   2048
#define DIM   1024
#define ATT   128
#define BN_ROWS (BATCH*SEQ)          // 16384

#define BM 128
#define BN 128
#define BK 32
#define BKP 40                        // padded smem stride (conflict-free frag loads)
#define THREADS 256

// ------------------------------- scratch ----------------------------------
__device__ __nv_bfloat16 g_xh[BN_ROWS * DIM];          // 33.5 MB
__device__ __nv_bfloat16 g_xl[BN_ROWS * DIM];
__device__ __nv_bfloat16 g_wth[256 * DIM];             // W^T combined [256][1024]
__device__ __nv_bfloat16 g_wtl[256 * DIM];
__device__ float         g_biasc[256];
__device__ __nv_bfloat16 g_fgh[BN_ROWS * 256];         // f|g combined
__device__ __nv_bfloat16 g_fgl[BN_ROWS * 256];
__device__ float         g_logits[(size_t)BATCH * SEQ * SEQ];   // 134 MB
__device__ __nv_bfloat16 g_ph[(size_t)BATCH * SEQ * SEQ];       // 67 MB
__device__ __nv_bfloat16 g_pl[(size_t)BATCH * SEQ * SEQ];       // 67 MB

// ------------------------------- helpers ----------------------------------
__device__ __forceinline__ void mma_bf16(float* c, const uint32_t* a, const uint32_t* b) {
    asm volatile(
        "mma.sync.aligned.m16n8k16.row.col.f32.bf16.bf16.f32 "
        "{%0,%1,%2,%3},{%4,%5,%6,%7},{%8,%9},{%0,%1,%2,%3};\n"
        : "+f"(c[0]), "+f"(c[1]), "+f"(c[2]), "+f"(c[3])
        : "r"(a[0]), "r"(a[1]), "r"(a[2]), "r"(a[3]), "r"(b[0]), "r"(b[1]));
}

__device__ __forceinline__ void split_store(float v, __nv_bfloat16* h, __nv_bfloat16* l) {
    __nv_bfloat16 hi = __float2bfloat16(v);
    *h = hi;
    *l = __float2bfloat16(v - __bfloat162float(hi));
}

// ------------------------------ prep kernels ------------------------------
__global__ void split_x_kernel(const float* __restrict__ x, int n4) {
    int i = blockIdx.x * blockDim.x + threadIdx.x;
    if (i >= n4) return;
    float4 v = ((const float4*)x)[i];
    float vv[4] = {v.x, v.y, v.z, v.w};
#pragma unroll
    for (int j = 0; j < 4; j++) {
        split_store(vv[j], &g_xh[(size_t)i * 4 + j], &g_xl[(size_t)i * 4 + j]);
    }
}

__global__ void split_w_kernel(const float* __restrict__ Wf, const float* __restrict__ Wg,
                               const float* __restrict__ bfp, const float* __restrict__ bgp) {
    int idx = blockIdx.x * blockDim.x + threadIdx.x;   // 262144 total
    if (idx < 256) g_biasc[idx] = (idx < 128) ? bfp[idx] : bgp[idx - 128];
    if (idx >= 256 * DIM) return;
    int n = idx >> 10;        // 0..255
    int k = idx & 1023;       // 0..1023
    float v = (n < 128) ? Wf[(size_t)k * ATT + n] : Wg[(size_t)k * ATT + (n - 128)];
    split_store(v, &g_wth[idx], &g_wtl[idx]);
}

// ------------------------------ split GEMM --------------------------------
// C[M,N] = A[M,K] @ B^T where A,B given as hi/lo bf16 pairs.
// If bTransposed: B stored [N,K] row-major (direct). Else B stored [K,N].
// Epilogue: v = acc + (epiAdd ? epiAdd[r*ldEpi + c] : 0);
//           optionally store fp32 (outF32) and/or split-bf16 (outH/outL).
__global__ __launch_bounds__(THREADS)
void gemm_split_kernel(
    const __nv_bfloat16* __restrict__ Ah, const __nv_bfloat16* __restrict__ Al,
    int lda, long long aBS,
    const __nv_bfloat16* __restrict__ Bh, const __nv_bfloat16* __restrict__ Bl,
    int ldb, long long bBS, int bTransposed,
    int K,
    float* outF32, int ldc, long long cBS,
    const float* epiAdd, int ldEpi, long long eBS,
    __nv_bfloat16* outH, __nv_bfloat16* outL)
{
    __shared__ __nv_bfloat16 As_h[BM][BKP], As_l[BM][BKP];
    __shared__ __nv_bfloat16 Bs_h[BN][BKP], Bs_l[BN][BKP];

    const int tid = threadIdx.x;
    const int m0 = blockIdx.y * BM;
    const int n0 = blockIdx.x * BN;
    const long long z = blockIdx.z;
    Ah += z * aBS;  Al += z * aBS;
    Bh += z * bBS;  Bl += z * bBS;
    if (outF32) outF32 += z * cBS;
    if (outH)   { outH += z * cBS; outL += z * cBS; }
    if (epiAdd) epiAdd += z * eBS;

    const int warp = tid >> 5;
    const int lane = tid & 31;
    const int gq   = lane >> 2;          // groupID 0..7
    const int tg2  = (lane & 3) * 2;     // 0,2,4,6
    const int rm   = (warp & 1) * 64;    // warp m-base within block
    const int cn   = (warp >> 1) * 32;   // warp n-base within block

    float acc[4][4][4];
#pragma unroll
    for (int i = 0; i < 4; i++)
#pragma unroll
        for (int j = 0; j < 4; j++)
#pragma unroll
            for (int e = 0; e < 4; e++) acc[i][j][e] = 0.f;

    for (int k0 = 0; k0 < K; k0 += BK) {
        // ---- load A tile (vector 8) ----
#pragma unroll
        for (int v = tid; v < BM * BK / 8; v += THREADS) {
            int row = v >> 2;
            int col = (v & 3) << 3;
            size_t off = (size_t)(m0 + row) * lda + k0 + col;
            *(uint4*)&As_h[row][col] = *(const uint4*)(Ah + off);
            *(uint4*)&As_l[row][col] = *(const uint4*)(Al + off);
        }
        // ---- load B tile ----
        if (bTransposed) {
#pragma unroll
            for (int v = tid; v < BN * BK / 8; v += THREADS) {
                int row = v >> 2;
                int col = (v & 3) << 3;
                size_t off = (size_t)(n0 + row) * ldb + k0 + col;
                *(uint4*)&Bs_h[row][col] = *(const uint4*)(Bh + off);
                *(uint4*)&Bs_l[row][col] = *(const uint4*)(Bl + off);
            }
        } else {
#pragma unroll
            for (int v = tid; v < BK * BN / 8; v += THREADS) {
                int kk = v >> 4;
                int nn = (v & 15) << 3;
                size_t off = (size_t)(k0 + kk) * ldb + n0 + nn;
                uint4 uh = *(const uint4*)(Bh + off);
                uint4 ul = *(const uint4*)(Bl + off);
                const __nv_bfloat16* phv = (const __nv_bfloat16*)&uh;
                const __nv_bfloat16* plv = (const __nv_bfloat16*)&ul;
#pragma unroll
                for (int j = 0; j < 8; j++) {
                    Bs_h[nn + j][kk] = phv[j];
                    Bs_l[nn + j][kk] = plv[j];
                }
            }
        }
        __syncthreads();

        // ---- compute ----
#pragma unroll
        for (int ks = 0; ks < BK; ks += 16) {
            uint32_t ah[4][4], al[4][4], bh[4][2], bl[4][2];
#pragma unroll
            for (int mi = 0; mi < 4; mi++) {
                int r = rm + mi * 16;
                ah[mi][0] = *(const uint32_t*)&As_h[r + gq    ][ks + tg2];
                ah[mi][1] = *(const uint32_t*)&As_h[r + gq + 8][ks + tg2];
                ah[mi][2] = *(const uint32_t*)&As_h[r + gq    ][ks + tg2 + 8];
                ah[mi][3] = *(const uint32_t*)&As_h[r + gq + 8][ks + tg2 + 8];
                al[mi][0] = *(const uint32_t*)&As_l[r + gq    ][ks + tg2];
                al[mi][1] = *(const uint32_t*)&As_l[r + gq + 8][ks + tg2];
                al[mi][2] = *(const uint32_t*)&As_l[r + gq    ][ks + tg2 + 8];
                al[mi][3] = *(const uint32_t*)&As_l[r + gq + 8][ks + tg2 + 8];
            }
#pragma unroll
            for (int ni = 0; ni < 4; ni++) {
                int c = cn + ni * 8;
                bh[ni][0] = *(const uint32_t*)&Bs_h[c + gq][ks + tg2];
                bh[ni][1] = *(const uint32_t*)&Bs_h[c + gq][ks + tg2 + 8];
                bl[ni][0] = *(const uint32_t*)&Bs_l[c + gq][ks + tg2];
                bl[ni][1] = *(const uint32_t*)&Bs_l[c + gq][ks + tg2 + 8];
            }
#pragma unroll
            for (int mi = 0; mi < 4; mi++)
#pragma unroll
                for (int ni = 0; ni < 4; ni++) {
                    mma_bf16(acc[mi][ni], ah[mi], bh[ni]);   // hi*hi
                    mma_bf16(acc[mi][ni], ah[mi], bl[ni]);   // hi*lo
                    mma_bf16(acc[mi][ni], al[mi], bh[ni]);   // lo*hi
                }
        }
        __syncthreads();
    }

    // ---- epilogue ----
#pragma unroll
    for (int mi = 0; mi < 4; mi++)
#pragma unroll
        for (int ni = 0; ni < 4; ni++) {
            int r0 = m0 + rm + mi * 16 + gq;
            int c0 = n0 + cn + ni * 8 + tg2;
#pragma unroll
            for (int e = 0; e < 4; e++) {
                int r = r0 + (e >> 1) * 8;
                int c = c0 + (e & 1);
                float v = acc[mi][ni][e];
                if (epiAdd) v += epiAdd[(size_t)r * ldEpi + c];
                if (outF32) outF32[(size_t)r * ldc + c] = v;
                if (outH)   split_store(v, &outH[(size_t)r * ldc + c],
                                           &outL[(size_t)r * ldc + c]);
            }
        }
}

// ------------------------------ softmax -----------------------------------
__global__ void softmax_kernel() {
    const size_t row = blockIdx.x;                      // 0..16383
    const float* L = g_logits + row * SEQ;
    const int tid = threadIdx.x;                        // 256 threads, 8 elems each
    __shared__ float red[THREADS];

    float v[8];
    float4 a = *(const float4*)(L + tid * 8);
    float4 b = *(const float4*)(L + tid * 8 + 4);
    v[0]=a.x; v[1]=a.y; v[2]=a.z; v[3]=a.w; v[4]=b.x; v[5]=b.y; v[6]=b.z; v[7]=b.w;

    float m = v[0];
#pragma unroll
    for (int i = 1; i < 8; i++) m = fmaxf(m, v[i]);
    red[tid] = m; __syncthreads();
    for (int s = THREADS / 2; s > 0; s >>= 1) {
        if (tid < s) red[tid] = fmaxf(red[tid], red[tid + s]);
        __syncthreads();
    }
    m = red[0]; __syncthreads();

    float sum = 0.f;
#pragma unroll
    for (int i = 0; i < 8; i++) { v[i] = expf(v[i] - m); sum += v[i]; }
    red[tid] = sum; __syncthreads();
    for (int s = THREADS / 2; s > 0; s >>= 1) {
        if (tid < s) red[tid] += red[tid + s];
        __syncthreads();
    }
    float inv = 1.f / red[0];

    size_t base = row * SEQ + tid * 8;
#pragma unroll
    for (int i = 0; i < 8; i++) {
        float p = v[i] * inv;
        split_store(p, &g_ph[base + i], &g_pl[base + i]);
    }
}

// ------------------------------ launcher ----------------------------------
extern "C" void kernel_launch(void* const* d_in, const int* in_sizes, int n_in,
                              void* d_out, int out_size) {
    const float* x  = (const float*)d_in[0];
    const float* Wf = (const float*)d_in[1];
    const float* bf = (const float*)d_in[2];
    const float* Wg = (const float*)d_in[3];
    const float* bg = (const float*)d_in[4];
    float* out = (float*)d_out;

    void *xh, *xl, *wth, *wtl, *biasc, *fgh, *fgl, *logits, *ph, *pl;
    cudaGetSymbolAddress(&xh, g_xh);
    cudaGetSymbolAddress(&xl, g_xl);
    cudaGetSymbolAddress(&wth, g_wth);
    cudaGetSymbolAddress(&wtl, g_wtl);
    cudaGetSymbolAddress(&biasc, g_biasc);
    cudaGetSymbolAddress(&fgh, g_fgh);
    cudaGetSymbolAddress(&fgl, g_fgl);
    cudaGetSymbolAddress(&logits, g_logits);
    cudaGetSymbolAddress(&ph, g_ph);
    cudaGetSymbolAddress(&pl, g_pl);

    // 1) split x into bf16 hi/lo
    split_x_kernel<<<(BN_ROWS * DIM / 4) / 256, 256>>>(x, BN_ROWS * DIM / 4);

    // 2) split+transpose W, build combined bias
    split_w_kernel<<<(256 * DIM) / 256, 256>>>(Wf, Wg, bf, bg);

    // 3) FG: [16384,256] = x[16384,1024] @ Wt^T   (Wt stored [256][1024])
    {
        dim3 grid(256 / BN, BN_ROWS / BM, 1);   // (2,128,1)
        gemm_split_kernel<<<grid, THREADS>>>(
            (const __nv_bfloat16*)xh, (const __nv_bfloat16*)xl, DIM, 0,
            (const __nv_bfloat16*)wth, (const __nv_bfloat16*)wtl, DIM, 0, 1,
            DIM,
            nullptr, 256, 0,
            (const float*)biasc, 0, 0,
            (__nv_bfloat16*)fgh, (__nv_bfloat16*)fgl);
    }

    // 4) LOGITS per batch: [2048,2048] = f @ g^T, K=128
    {
        dim3 grid(SEQ / BN, SEQ / BM, BATCH);   // (16,16,8)
        const __nv_bfloat16* fh = (const __nv_bfloat16*)fgh;
        const __nv_bfloat16* fl = (const __nv_bfloat16*)fgl;
        gemm_split_kernel<<<grid, THREADS>>>(
            fh,        fl,        256, (long long)SEQ * 256,
            fh + 128,  fl + 128,  256, (long long)SEQ * 256, 1,
            ATT,
            (float*)logits, SEQ, (long long)SEQ * SEQ,
            nullptr, 0, 0,
            nullptr, nullptr);
    }

    // 5) row softmax + split-store P
    softmax_kernel<<<BN_ROWS, THREADS>>>();

    // 6) AV per batch: out[2048,1024] = P @ x + x
    {
        dim3 grid(DIM / BN, SEQ / BM, BATCH);   // (8,16,8)
        gemm_split_kernel<<<grid, THREADS>>>(
            (const __nv_bfloat16*)ph, (const __nv_bfloat16*)pl, SEQ, (long long)SEQ * SEQ,
            (const __nv_bfloat16*)xh, (const __nv_bfloat16*)xl, DIM, (long long)SEQ * DIM, 0,
            SEQ,
            out, DIM, (long long)SEQ * DIM,
            x, DIM, (long long)SEQ * DIM,
            nullptr, nullptr);
    }
}

// round 3
// speedup vs baseline: 1.9521x; 1.9521x over previous
#include <cuda_runtime.h>
#include <cuda_bf16.h>
#include <cstdint>

// ---------------------------------------------------------------------------
// SelfAttention: B=8, N=2048, D=1024, ATT=128
//   f|g = x@[Wf|Wg] + bias ; att = softmax(f@g^T) ; out = att@x + x
// GEMMs: mma.sync m16n8k16 bf16 with hi/lo 3-way split (fp32-equivalent,
// ~2e-5 rel), term-outer MMA ordering (no accumulator RAW chains),
// cp.async 3-stage pipeline. tcgen05 is unavailable (harness PTX targets
// sm_103 without the 'a' feature suffix).
// ---------------------------------------------------------------------------

#define BATCH 8
#define SEQ   2048
#define DIM   1024
#define ATT   128
#define BN_ROWS (BATCH*SEQ)          // 16384

#define THREADS 256
#define BK 32
#define APITCH 80                    // bytes per smem row (40 bf16, conflict-free)
#define ARR_BYTES (128*APITCH)       // 10240
#define STAGE_BYTES (4*ARR_BYTES)    // 40960: Ah|Al|Bh|Bl
#define STAGES 3
#define SMEM_TOTAL (STAGES*STAGE_BYTES)   // 122880

// ------------------------------- scratch ----------------------------------
__device__ __nv_bfloat16 g_xh[BN_ROWS * DIM];
__device__ __nv_bfloat16 g_xl[BN_ROWS * DIM];
__device__ __nv_bfloat16 g_xth[(size_t)BATCH * DIM * SEQ];   // x^T per batch
__device__ __nv_bfloat16 g_xtl[(size_t)BATCH * DIM * SEQ];
__device__ __nv_bfloat16 g_wth[256 * DIM];
__device__ __nv_bfloat16 g_wtl[256 * DIM];
__device__ float         g_biasc[256];
__device__ __nv_bfloat16 g_fgh[BN_ROWS * 256];
__device__ __nv_bfloat16 g_fgl[BN_ROWS * 256];
__device__ float         g_logits[(size_t)BATCH * SEQ * SEQ];
__device__ __nv_bfloat16 g_ph[(size_t)BATCH * SEQ * SEQ];
__device__ __nv_bfloat16 g_pl[(size_t)BATCH * SEQ * SEQ];

// ------------------------------- helpers ----------------------------------
__device__ __forceinline__ void mma_bf16(float* c, const uint32_t* a, const uint32_t* b) {
    asm volatile(
        "mma.sync.aligned.m16n8k16.row.col.f32.bf16.bf16.f32 "
        "{%0,%1,%2,%3},{%4,%5,%6,%7},{%8,%9},{%0,%1,%2,%3};\n"
        : "+f"(c[0]), "+f"(c[1]), "+f"(c[2]), "+f"(c[3])
        : "r"(a[0]), "r"(a[1]), "r"(a[2]), "r"(a[3]), "r"(b[0]), "r"(b[1]));
}
__device__ __forceinline__ void cp16(void* dst, const void* src) {
    uint32_t d = (uint32_t)__cvta_generic_to_shared(dst);
    asm volatile("cp.async.cg.shared.global [%0], [%1], 16;" :: "r"(d), "l"(src));
}
#define CP_COMMIT() asm volatile("cp.async.commit_group;" ::: "memory")
#define CP_WAIT(n)  asm volatile("cp.async.wait_group %0;" :: "n"(n) : "memory")

__device__ __forceinline__ void split_store(float v, __nv_bfloat16* h, __nv_bfloat16* l) {
    __nv_bfloat16 hi = __float2bfloat16(v);
    *h = hi;
    *l = __float2bfloat16(v - __bfloat162float(hi));
}

// ------------------------------ prep kernels ------------------------------
__global__ void split_x_kernel(const float* __restrict__ x, int n4) {
    int i = blockIdx.x * blockDim.x + threadIdx.x;
    if (i >= n4) return;
    float4 v = ((const float4*)x)[i];
    float vv[4] = {v.x, v.y, v.z, v.w};
#pragma unroll
    for (int j = 0; j < 4; j++)
        split_store(vv[j], &g_xh[(size_t)i * 4 + j], &g_xl[(size_t)i * 4 + j]);
}

__global__ void split_w_kernel(const float* __restrict__ Wf, const float* __restrict__ Wg,
                               const float* __restrict__ bfp, const float* __restrict__ bgp) {
    int idx = blockIdx.x * blockDim.x + threadIdx.x;
    if (idx < 256) g_biasc[idx] = (idx < 128) ? bfp[idx] : bgp[idx - 128];
    if (idx >= 256 * DIM) return;
    int n = idx >> 10;
    int k = idx & 1023;
    float v = (n < 128) ? Wf[(size_t)k * ATT + n] : Wg[(size_t)k * ATT + (n - 128)];
    split_store(v, &g_wth[idx], &g_wtl[idx]);
}

// x [b][n][d] -> xT hi/lo [b][d][n]
__global__ void transpose_split_kernel(const float* __restrict__ x) {
    __shared__ float tile[32][33];
    int b = blockIdx.z;
    int n0 = blockIdx.x * 32, d0 = blockIdx.y * 32;
    int tx = threadIdx.x, ty = threadIdx.y;           // (32, 8)
    const float* xb = x + (size_t)b * SEQ * DIM;
#pragma unroll
    for (int j = 0; j < 4; j++)
        tile[ty + 8 * j][tx] = xb[(size_t)(n0 + ty + 8 * j) * DIM + d0 + tx];
    __syncthreads();
    size_t base = (size_t)b * DIM * SEQ;
#pragma unroll
    for (int j = 0; j < 4; j++) {
        float v = tile[tx][ty + 8 * j];
        size_t o = base + (size_t)(d0 + ty + 8 * j) * SEQ + n0 + tx;
        split_store(v, &g_xth[o], &g_xtl[o]);
    }
}

// --------------------------- pipelined split GEMM -------------------------
// C[128,128] per CTA. A [M,K] hi/lo K-major; B [N,K] hi/lo K-major.
__global__ __launch_bounds__(THREADS, 1)
void gemm_split_kernel(
    const __nv_bfloat16* __restrict__ Ah, const __nv_bfloat16* __restrict__ Al,
    int lda, long long aBS,
    const __nv_bfloat16* __restrict__ Bh, const __nv_bfloat16* __restrict__ Bl,
    int ldb, long long bBS,
    int K,
    float* outF32, int ldc, long long cBS,
    const float* epiAdd, int ldEpi, long long eBS,
    const float* biasRow,
    __nv_bfloat16* outH, __nv_bfloat16* outL)
{
    extern __shared__ char smem[];

    const int tid = threadIdx.x;
    const int m0 = blockIdx.y * 128;
    const int n0 = blockIdx.x * 128;
    const long long z = blockIdx.z;
    Ah += z * aBS;  Al += z * aBS;
    Bh += z * bBS;  Bl += z * bBS;
    if (outF32) outF32 += z * cBS;
    if (outH)   { outH += z * cBS; outL += z * cBS; }
    if (epiAdd) epiAdd += z * eBS;

    const int warp = tid >> 5;
    const int lane = tid & 31;
    const int gq   = lane >> 2;
    const int tg2  = (lane & 3) * 2;
    const int rm   = (warp & 1) * 64;
    const int cn   = (warp >> 1) * 32;

    const __nv_bfloat16* Arow_h = Ah + (size_t)m0 * lda;
    const __nv_bfloat16* Arow_l = Al + (size_t)m0 * lda;
    const __nv_bfloat16* Brow_h = Bh + (size_t)n0 * ldb;
    const __nv_bfloat16* Brow_l = Bl + (size_t)n0 * ldb;

    // per-thread fixed load assignment: 2 chunks per array per stage
    const int r0c = tid >> 2;            // rows: r0c, r0c+64
    const int cc  = (tid & 3) * 16;      // byte offset of 16B chunk within 64B row

    float acc[4][4][4];
#pragma unroll
    for (int i = 0; i < 4; i++)
#pragma unroll
        for (int j = 0; j < 4; j++)
#pragma unroll
            for (int e = 0; e < 4; e++) acc[i][j][e] = 0.f;

    const int T = K >> 5;                // K-tiles of 32

    auto load_stage = [&](int s, int t) {
        const int k0 = t * BK;
        char* st = smem + s * STAGE_BYTES;
#pragma unroll
        for (int i = 0; i < 2; i++) {
            int row = r0c + i * 64;
            uint32_t doff = (uint32_t)row * APITCH + cc;
            const char* sAh = (const char*)(Arow_h + (size_t)row * lda + k0) + cc;
            const char* sAl = (const char*)(Arow_l + (size_t)row * lda + k0) + cc;
            const char* sBh = (const char*)(Brow_h + (size_t)row * ldb + k0) + cc;
            const char* sBl = (const char*)(Brow_l + (size_t)row * ldb + k0) + cc;
            cp16(st + doff,                 sAh);
            cp16(st + ARR_BYTES + doff,     sAl);
            cp16(st + 2 * ARR_BYTES + doff, sBh);
            cp16(st + 3 * ARR_BYTES + doff, sBl);
        }
    };

#pragma unroll
    for (int s = 0; s < STAGES; s++) {
        if (s < T) load_stage(s, s);
        CP_COMMIT();
    }

    for (int t = 0; t < T; t++) {
        CP_WAIT(STAGES - 1);
        __syncthreads();

        const char* st = smem + (t % STAGES) * STAGE_BYTES;
#pragma unroll
        for (int ks = 0; ks < BK; ks += 16) {
            uint32_t ah[4][4], al[4][4], bh[4][2], bl[4][2];
#pragma unroll
            for (int mi = 0; mi < 4; mi++) {
#pragma unroll
                for (int q = 0; q < 4; q++) {
                    int row = rm + mi * 16 + gq + (q & 1) * 8;
                    int col = ks + tg2 + (q >> 1) * 8;
                    ah[mi][q] = *(const uint32_t*)(st + row * APITCH + col * 2);
                    al[mi][q] = *(const uint32_t*)(st + ARR_BYTES + row * APITCH + col * 2);
                }
            }
#pragma unroll
            for (int ni = 0; ni < 4; ni++) {
#pragma unroll
                for (int q = 0; q < 2; q++) {
                    int row = cn + ni * 8 + gq;
                    int col = ks + tg2 + q * 8;
                    bh[ni][q] = *(const uint32_t*)(st + 2 * ARR_BYTES + row * APITCH + col * 2);
                    bl[ni][q] = *(const uint32_t*)(st + 3 * ARR_BYTES + row * APITCH + col * 2);
                }
            }
            // term-outer ordering: 16 independent MMAs between accumulator reuse
#pragma unroll
            for (int mi = 0; mi < 4; mi++)
#pragma unroll
                for (int ni = 0; ni < 4; ni++)
                    mma_bf16(acc[mi][ni], ah[mi], bh[ni]);
#pragma unroll
            for (int mi = 0; mi < 4; mi++)
#pragma unroll
                for (int ni = 0; ni < 4; ni++)
                    mma_bf16(acc[mi][ni], ah[mi], bl[ni]);
#pragma unroll
            for (int mi = 0; mi < 4; mi++)
#pragma unroll
                for (int ni = 0; ni < 4; ni++)
                    mma_bf16(acc[mi][ni], al[mi], bh[ni]);
        }
        __syncthreads();
        if (t + STAGES < T) load_stage(t % STAGES, t + STAGES);
        CP_COMMIT();
    }

    // ------------------------------ epilogue -------------------------------
#pragma unroll
    for (int mi = 0; mi < 4; mi++)
#pragma unroll
        for (int ni = 0; ni < 4; ni++) {
            int r0 = m0 + rm + mi * 16 + gq;
            int c0 = n0 + cn + ni * 8 + tg2;
#pragma unroll
            for (int e = 0; e < 4; e++) {
                int r = r0 + (e >> 1) * 8;
                int c = c0 + (e & 1);
                float v = acc[mi][ni][e];
                if (biasRow) v += biasRow[c];
                if (epiAdd)  v += epiAdd[(size_t)r * ldEpi + c];
                if (outF32)  outF32[(size_t)r * ldc + c] = v;
                if (outH)    split_store(v, &outH[(size_t)r * ldc + c],
                                            &outL[(size_t)r * ldc + c]);
            }
        }
}

// ------------------------------ softmax -----------------------------------
__global__ void softmax_kernel() {
    const size_t row = blockIdx.x;
    const float* L = g_logits + row * SEQ;
    const int tid = threadIdx.x;
    __shared__ float red[THREADS];

    float v[8];
    float4 a = *(const float4*)(L + tid * 8);
    float4 b = *(const float4*)(L + tid * 8 + 4);
    v[0]=a.x; v[1]=a.y; v[2]=a.z; v[3]=a.w; v[4]=b.x; v[5]=b.y; v[6]=b.z; v[7]=b.w;

    float m = v[0];
#pragma unroll
    for (int i = 1; i < 8; i++) m = fmaxf(m, v[i]);
    red[tid] = m; __syncthreads();
    for (int s = THREADS / 2; s > 0; s >>= 1) {
        if (tid < s) red[tid] = fmaxf(red[tid], red[tid + s]);
        __syncthreads();
    }
    m = red[0]; __syncthreads();

    float sum = 0.f;
#pragma unroll
    for (int i = 0; i < 8; i++) { v[i] = __expf(v[i] - m); sum += v[i]; }
    red[tid] = sum; __syncthreads();
    for (int s = THREADS / 2; s > 0; s >>= 1) {
        if (tid < s) red[tid] += red[tid + s];
        __syncthreads();
    }
    float inv = 1.f / red[0];

    size_t base = row * SEQ + tid * 8;
#pragma unroll
    for (int i = 0; i < 8; i++) {
        float p = v[i] * inv;
        split_store(p, &g_ph[base + i], &g_pl[base + i]);
    }
}

// ------------------------------ launcher ----------------------------------
extern "C" void kernel_launch(void* const* d_in, const int* in_sizes, int n_in,
                              void* d_out, int out_size) {
    const float* x  = (const float*)d_in[0];
    const float* Wf = (const float*)d_in[1];
    const float* bf = (const float*)d_in[2];
    const float* Wg = (const float*)d_in[3];
    const float* bg = (const float*)d_in[4];
    float* out = (float*)d_out;

    cudaFuncSetAttribute(gemm_split_kernel,
                         cudaFuncAttributeMaxDynamicSharedMemorySize, SMEM_TOTAL);

    void *xh, *xl, *xth, *xtl, *wth, *wtl, *biasc, *fgh, *fgl, *logits, *ph, *pl;
    cudaGetSymbolAddress(&xh, g_xh);
    cudaGetSymbolAddress(&xl, g_xl);
    cudaGetSymbolAddress(&xth, g_xth);
    cudaGetSymbolAddress(&xtl, g_xtl);
    cudaGetSymbolAddress(&wth, g_wth);
    cudaGetSymbolAddress(&wtl, g_wtl);
    cudaGetSymbolAddress(&biasc, g_biasc);
    cudaGetSymbolAddress(&fgh, g_fgh);
    cudaGetSymbolAddress(&fgl, g_fgl);
    cudaGetSymbolAddress(&logits, g_logits);
    cudaGetSymbolAddress(&ph, g_ph);
    cudaGetSymbolAddress(&pl, g_pl);

    // 1) split x hi/lo (A operand, row-major)
    split_x_kernel<<<(BN_ROWS * DIM / 4) / 256, 256>>>(x, BN_ROWS * DIM / 4);
    // 2) split + transpose W, combined bias
    split_w_kernel<<<(256 * DIM) / 256, 256>>>(Wf, Wg, bf, bg);
    // 3) transpose-split x -> xT hi/lo (B operand for AV, K-major)
    {
        dim3 grid(SEQ / 32, DIM / 32, BATCH);
        transpose_split_kernel<<<grid, dim3(32, 8)>>>(x);
    }

    // 4) FG: [16384,256] = x @ W^T + bias -> split
    {
        dim3 grid(256 / 128, BN_ROWS / 128, 1);
        gemm_split_kernel<<<grid, THREADS, SMEM_TOTAL>>>(
            (const __nv_bfloat16*)xh, (const __nv_bfloat16*)xl, DIM, 0,
            (const __nv_bfloat16*)wth, (const __nv_bfloat16*)wtl, DIM, 0,
            DIM,
            nullptr, 256, 0,
            nullptr, 0, 0,
            (const float*)biasc,
            (__nv_bfloat16*)fgh, (__nv_bfloat16*)fgl);
    }

    // 5) LOGITS per batch: [2048,2048] = f @ g^T (K=128)
    {
        dim3 grid(SEQ / 128, SEQ / 128, BATCH);
        const __nv_bfloat16* fh = (const __nv_bfloat16*)fgh;
        const __nv_bfloat16* fl = (const __nv_bfloat16*)fgl;
        gemm_split_kernel<<<grid, THREADS, SMEM_TOTAL>>>(
            fh,       fl,       256, (long long)SEQ * 256,
            fh + 128, fl + 128, 256, (long long)SEQ * 256,
            ATT,
            (float*)logits, SEQ, (long long)SEQ * SEQ,
            nullptr, 0, 0,
            nullptr,
            nullptr, nullptr);
    }

    // 6) softmax + split P
    softmax_kernel<<<BN_ROWS, THREADS>>>();

    // 7) AV per batch: out = P @ x + x (B = xT, K-major)
    {
        dim3 grid(DIM / 128, SEQ / 128, BATCH);
        gemm_split_kernel<<<grid, THREADS, SMEM_TOTAL>>>(
            (const __nv_bfloat16*)ph, (const __nv_bfloat16*)pl, SEQ, (long long)SEQ * SEQ,
            (const __nv_bfloat16*)xth, (const __nv_bfloat16*)xtl, SEQ, (long long)DIM * SEQ,
            SEQ,
            out, DIM, (long long)SEQ * DIM,
            x, DIM, (long long)SEQ * DIM,
            nullptr,
            nullptr, nullptr);
    }
}

// round 4
// speedup vs baseline: 3.9091x; 2.0025x over previous
#include <cuda_runtime.h>
#include <cuda_bf16.h>
#include <cuda_fp16.h>
#include <cstdint>

// ---------------------------------------------------------------------------
// SelfAttention B=8 N=2048 D=1024 ATT=128
//   FG: bf16 hi/lo 3-term split GEMM (fp32-equiv) -> f|g
//   fused logits+softmax: 2-pass S-recompute, no-max softmax (sigma~11, safe),
//       P stored fp16
//   AV: plain fp16 single-term GEMM (error ~3e-4), 2 CTAs/SM
// All tensor work via mma.sync m16n8k16 + ldmatrix.x4 (tcgen05 not available:
// harness ptxas targets sm_103 without 'a' features).
// ---------------------------------------------------------------------------

#define BATCH 8
#define SEQ   2048
#define DIM   1024
#define BN_ROWS (BATCH*SEQ)

#define THREADS 256
#define BK 32
#define APITCH 80
#define ARR_BYTES (128*APITCH)
#define FG_STAGE (4*ARR_BYTES)
#define FG_STAGES 3
#define FG_SMEM (FG_STAGES*FG_STAGE)
#define AV_STAGE (2*ARR_BYTES)
#define AV_STAGES 3
#define AV_SMEM (AV_STAGES*AV_STAGE)
#define FPITCH 272
#define FARR (128*FPITCH)
#define GOFF0 (2*FARR)
#define REDOFF (6*FARR)
#define FUSED_SMEM (REDOFF + 2048)

// ------------------------------- scratch ----------------------------------
__device__ __nv_bfloat16 g_xh[BN_ROWS * DIM];
__device__ __nv_bfloat16 g_xl[BN_ROWS * DIM];
__device__ __half        g_xt[(size_t)BATCH * DIM * SEQ];
__device__ __nv_bfloat16 g_wth[256 * DIM];
__device__ __nv_bfloat16 g_wtl[256 * DIM];
__device__ float         g_biasc[256];
__device__ __nv_bfloat16 g_fgh[BN_ROWS * 256];
__device__ __nv_bfloat16 g_fgl[BN_ROWS * 256];
__device__ __half        g_p[(size_t)BATCH * SEQ * SEQ];

// ------------------------------- helpers ----------------------------------
__device__ __forceinline__ uint32_t smem_u32(const void* p) {
    uint32_t a;
    asm("{ .reg .u64 t; cvta.to.shared.u64 t, %1; cvt.u32.u64 %0, t; }"
        : "=r"(a) : "l"(p));
    return a;
}
__device__ __forceinline__ void mma_bf16(float* c, const uint32_t* a, const uint32_t* b) {
    asm volatile(
        "mma.sync.aligned.m16n8k16.row.col.f32.bf16.bf16.f32 "
        "{%0,%1,%2,%3},{%4,%5,%6,%7},{%8,%9},{%0,%1,%2,%3};\n"
        : "+f"(c[0]), "+f"(c[1]), "+f"(c[2]), "+f"(c[3])
        : "r"(a[0]), "r"(a[1]), "r"(a[2]), "r"(a[3]), "r"(b[0]), "r"(b[1]));
}
__device__ __forceinline__ void mma_f16(float* c, const uint32_t* a, const uint32_t* b) {
    asm volatile(
        "mma.sync.aligned.m16n8k16.row.col.f32.f16.f16.f32 "
        "{%0,%1,%2,%3},{%4,%5,%6,%7},{%8,%9},{%0,%1,%2,%3};\n"
        : "+f"(c[0]), "+f"(c[1]), "+f"(c[2]), "+f"(c[3])
        : "r"(a[0]), "r"(a[1]), "r"(a[2]), "r"(a[3]), "r"(b[0]), "r"(b[1]));
}
__device__ __forceinline__ void ldsm_x4(uint32_t* r, uint32_t addr) {
    asm volatile("ldmatrix.sync.aligned.m8n8.x4.shared.b16 {%0,%1,%2,%3}, [%4];"
        : "=r"(r[0]), "=r"(r[1]), "=r"(r[2]), "=r"(r[3]) : "r"(addr));
}
__device__ __forceinline__ void cp16(void* dst, const void* src) {
    uint32_t d = (uint32_t)__cvta_generic_to_shared(dst);
    asm volatile("cp.async.cg.shared.global [%0], [%1], 16;" :: "r"(d), "l"(src));
}
#define CP_COMMIT() asm volatile("cp.async.commit_group;" ::: "memory")
#define CP_WAIT(n)  asm volatile("cp.async.wait_group %0;" :: "n"(n) : "memory")

__device__ __forceinline__ void split_store(float v, __nv_bfloat16* h, __nv_bfloat16* l) {
    __nv_bfloat16 hi = __float2bfloat16(v);
    *h = hi;
    *l = __float2bfloat16(v - __bfloat162float(hi));
}

// ------------------------------ prep kernels ------------------------------
__global__ void split_x_kernel(const float* __restrict__ x, int n4) {
    int i = blockIdx.x * blockDim.x + threadIdx.x;
    if (i >= n4) return;
    float4 v = ((const float4*)x)[i];
    float vv[4] = {v.x, v.y, v.z, v.w};
#pragma unroll
    for (int j = 0; j < 4; j++)
        split_store(vv[j], &g_xh[(size_t)i * 4 + j], &g_xl[(size_t)i * 4 + j]);
}

__global__ void split_w_kernel(const float* __restrict__ Wf, const float* __restrict__ Wg,
                               const float* __restrict__ bfp, const float* __restrict__ bgp) {
    int idx = blockIdx.x * blockDim.x + threadIdx.x;
    if (idx < 256) g_biasc[idx] = (idx < 128) ? bfp[idx] : bgp[idx - 128];
    if (idx >= 256 * DIM) return;
    int n = idx >> 10;
    int k = idx & 1023;
    float v = (n < 128) ? Wf[(size_t)k * 128 + n] : Wg[(size_t)k * 128 + (n - 128)];
    split_store(v, &g_wth[idx], &g_wtl[idx]);
}

__global__ void transpose_half_kernel(const float* __restrict__ x) {
    __shared__ float tile[32][33];
    int b = blockIdx.z;
    int n0 = blockIdx.x * 32, d0 = blockIdx.y * 32;
    int tx = threadIdx.x, ty = threadIdx.y;
    const float* xb = x + (size_t)b * SEQ * DIM;
#pragma unroll
    for (int j = 0; j < 4; j++)
        tile[ty + 8 * j][tx] = xb[(size_t)(n0 + ty + 8 * j) * DIM + d0 + tx];
    __syncthreads();
    size_t base = (size_t)b * DIM * SEQ;
#pragma unroll
    for (int j = 0; j < 4; j++) {
        float v = tile[tx][ty + 8 * j];
        g_xt[base + (size_t)(d0 + ty + 8 * j) * SEQ + n0 + tx] = __float2half(v);
    }
}

// --------------------- FG: bf16 split GEMM (ldmatrix) ---------------------
__global__ __launch_bounds__(THREADS, 1)
void fg_gemm_kernel(const __nv_bfloat16* __restrict__ Ah, const __nv_bfloat16* __restrict__ Al,
                    const __nv_bfloat16* __restrict__ Bh, const __nv_bfloat16* __restrict__ Bl)
{
    extern __shared__ char smem[];
    const uint32_t sb = smem_u32(smem);
    const int tid = threadIdx.x;
    const int m0 = blockIdx.y * 128;
    const int n0 = blockIdx.x * 128;
    const int warp = tid >> 5;
    const int lane = tid & 31;
    const int gq   = lane >> 2;
    const int tg2  = (lane & 3) * 2;
    const int rm   = (warp & 1) * 64;
    const int cn   = (warp >> 1) * 32;

    const uint32_t aoff = (uint32_t)(rm + (lane & 15)) * APITCH + (uint32_t)(lane >> 4) * 16;
    const uint32_t boff = (uint32_t)(cn + (lane & 7) + ((lane >> 4) & 1) * 8) * APITCH
                        + (uint32_t)((lane >> 3) & 1) * 16;

    const __nv_bfloat16* Arow_h = Ah + (size_t)m0 * DIM;
    const __nv_bfloat16* Arow_l = Al + (size_t)m0 * DIM;
    const __nv_bfloat16* Brow_h = Bh + (size_t)n0 * DIM;
    const __nv_bfloat16* Brow_l = Bl + (size_t)n0 * DIM;

    const int r0c = tid >> 2;
    const int cc  = (tid & 3) * 16;

    float acc[4][4][4];
#pragma unroll
    for (int i = 0; i < 4; i++)
#pragma unroll
        for (int j = 0; j < 4; j++)
#pragma unroll
            for (int e = 0; e < 4; e++) acc[i][j][e] = 0.f;

    const int T = DIM / BK;

    auto load_stage = [&](int s, int t) {
        const int k0 = t * BK;
        char* st = smem + s * FG_STAGE;
#pragma unroll
        for (int i = 0; i < 2; i++) {
            int row = r0c + i * 64;
            uint32_t doff = (uint32_t)row * APITCH + cc;
            cp16(st + doff,                 (const char*)(Arow_h + (size_t)row * DIM + k0) + cc);
            cp16(st + ARR_BYTES + doff,     (const char*)(Arow_l + (size_t)row * DIM + k0) + cc);
            cp16(st + 2 * ARR_BYTES + doff, (const char*)(Brow_h + (size_t)row * DIM + k0) + cc);
            cp16(st + 3 * ARR_BYTES + doff, (const char*)(Brow_l + (size_t)row * DIM + k0) + cc);
        }
    };

#pragma unroll
    for (int s = 0; s < FG_STAGES; s++) { load_stage(s, s); CP_COMMIT(); }

    for (int t = 0; t < T; t++) {
        CP_WAIT(FG_STAGES - 1);
        __syncthreads();
        const uint32_t stA = sb + (t % FG_STAGES) * FG_STAGE;
        const uint32_t stB = stA + 2 * ARR_BYTES;
#pragma unroll
        for (int ks = 0; ks < BK; ks += 16) {
            uint32_t ah[4][4], al[4][4], bh[4][2], bl[4][2];
#pragma unroll
            for (int mi = 0; mi < 4; mi++) {
                ldsm_x4(ah[mi], stA + aoff + mi * (16 * APITCH) + ks * 2);
                ldsm_x4(al[mi], stA + ARR_BYTES + aoff + mi * (16 * APITCH) + ks * 2);
            }
#pragma unroll
            for (int pr = 0; pr < 2; pr++) {
                uint32_t t4[4];
                ldsm_x4(t4, stB + boff + pr * (16 * APITCH) + ks * 2);
                bh[2 * pr][0] = t4[0]; bh[2 * pr][1] = t4[1];
                bh[2 * pr + 1][0] = t4[2]; bh[2 * pr + 1][1] = t4[3];
                ldsm_x4(t4, stB + ARR_BYTES + boff + pr * (16 * APITCH) + ks * 2);
                bl[2 * pr][0] = t4[0]; bl[2 * pr][1] = t4[1];
                bl[2 * pr + 1][0] = t4[2]; bl[2 * pr + 1][1] = t4[3];
            }
#pragma unroll
            for (int mi = 0; mi < 4; mi++)
#pragma unroll
                for (int ni = 0; ni < 4; ni++)
                    mma_bf16(acc[mi][ni], ah[mi], bh[ni]);
#pragma unroll
            for (int mi = 0; mi < 4; mi++)
#pragma unroll
                for (int ni = 0; ni < 4; ni++)
                    mma_bf16(acc[mi][ni], ah[mi], bl[ni]);
#pragma unroll
            for (int mi = 0; mi < 4; mi++)
#pragma unroll
                for (int ni = 0; ni < 4; ni++)
                    mma_bf16(acc[mi][ni], al[mi], bh[ni]);
        }
        __syncthreads();
        if (t + FG_STAGES < T) load_stage(t % FG_STAGES, t + FG_STAGES);
        CP_COMMIT();
    }

#pragma unroll
    for (int mi = 0; mi < 4; mi++)
#pragma unroll
        for (int ni = 0; ni < 4; ni++) {
            int r0 = m0 + rm + mi * 16 + gq;
            int c0 = n0 + cn + ni * 8 + tg2;
#pragma unroll
            for (int e = 0; e < 4; e++) {
                int r = r0 + (e >> 1) * 8;
                int c = c0 + (e & 1);
                float v = acc[mi][ni][e] + g_biasc[c];
                split_store(v, &g_fgh[(size_t)r * 256 + c], &g_fgl[(size_t)r * 256 + c]);
            }
        }
}

// --------------- fused logits + softmax + P(fp16) kernel -------------------
__global__ __launch_bounds__(THREADS, 1)
void fused_attn_kernel()
{
    extern __shared__ char smem[];
    const uint32_t sb = smem_u32(smem);
    float* redS = (float*)(smem + REDOFF);

    const int tid = threadIdx.x;
    const int warp = tid >> 5;
    const int lane = tid & 31;
    const int gq   = lane >> 2;
    const int tg2  = (lane & 3) * 2;
    const int rm   = (warp & 1) * 64;
    const int cn   = (warp >> 1) * 32;
    const int m0 = blockIdx.x * 128;
    const int b  = blockIdx.y;

    const uint32_t aoff = (uint32_t)(rm + (lane & 15)) * FPITCH + (uint32_t)(lane >> 4) * 16;
    const uint32_t boff = (uint32_t)(cn + (lane & 7) + ((lane >> 4) & 1) * 8) * FPITCH
                        + (uint32_t)((lane >> 3) & 1) * 16;

    const size_t rowbase = (size_t)b * SEQ;

#pragma unroll
    for (int i = 0; i < 8; i++) {
        int idx = tid + i * THREADS;
        int row = idx >> 4;
        int c = (idx & 15) * 16;
        char* dst = smem + row * FPITCH + c;
        cp16(dst,        (const char*)(g_fgh + (rowbase + m0 + row) * 256) + c);
        cp16(dst + FARR, (const char*)(g_fgl + (rowbase + m0 + row) * 256) + c);
    }
    auto load_g = [&](int s, int nt) {
        char* st = smem + GOFF0 + s * (2 * FARR);
#pragma unroll
        for (int i = 0; i < 8; i++) {
            int idx = tid + i * THREADS;
            int row = idx >> 4;
            int c = (idx & 15) * 16;
            char* dst = st + row * FPITCH + c;
            cp16(dst,        (const char*)(g_fgh + (rowbase + nt * 128 + row) * 256 + 128) + c);
            cp16(dst + FARR, (const char*)(g_fgl + (rowbase + nt * 128 + row) * 256 + 128) + c);
        }
    };

    load_g(0, 0);
    CP_COMMIT();
    load_g(1, 1);
    CP_COMMIT();

    float s_run[4][2] = {{0.f, 0.f}, {0.f, 0.f}, {0.f, 0.f}, {0.f, 0.f}};
    float rowInv[4][2];

    for (int tt = 0; tt < 32; tt++) {
        CP_WAIT(1);
        __syncthreads();
        const int stage = tt & 1;
        const int nt = tt & 15;
        const uint32_t stG = sb + GOFF0 + stage * (2 * FARR);

        float acc[4][4][4];
#pragma unroll
        for (int i = 0; i < 4; i++)
#pragma unroll
            for (int j = 0; j < 4; j++)
#pragma unroll
                for (int e = 0; e < 4; e++) acc[i][j][e] = 0.f;

#pragma unroll
        for (int ksb = 0; ksb < 8; ksb++) {
            const int ks = ksb * 16;
            uint32_t ah[4][4], al[4][4], bh[4][2], bl[4][2];
#pragma unroll
            for (int mi = 0; mi < 4; mi++) {
                ldsm_x4(ah[mi], sb + aoff + mi * (16 * FPITCH) + ks * 2);
                ldsm_x4(al[mi], sb + FARR + aoff + mi * (16 * FPITCH) + ks * 2);
            }
#pragma unroll
            for (int pr = 0; pr < 2; pr++) {
                uint32_t t4[4];
                ldsm_x4(t4, stG + boff + pr * (16 * FPITCH) + ks * 2);
                bh[2 * pr][0] = t4[0]; bh[2 * pr][1] = t4[1];
                bh[2 * pr + 1][0] = t4[2]; bh[2 * pr + 1][1] = t4[3];
                ldsm_x4(t4, stG + FARR + boff + pr * (16 * FPITCH) + ks * 2);
                bl[2 * pr][0] = t4[0]; bl[2 * pr][1] = t4[1];
                bl[2 * pr + 1][0] = t4[2]; bl[2 * pr + 1][1] = t4[3];
            }
#pragma unroll
            for (int mi = 0; mi < 4; mi++)
#pragma unroll
                for (int ni = 0; ni < 4; ni++)
                    mma_bf16(acc[mi][ni], ah[mi], bh[ni]);
#pragma unroll
            for (int mi = 0; mi < 4; mi++)
#pragma unroll
                for (int ni = 0; ni < 4; ni++)
                    mma_bf16(acc[mi][ni], ah[mi], bl[ni]);
#pragma unroll
            for (int mi = 0; mi < 4; mi++)
#pragma unroll
                for (int ni = 0; ni < 4; ni++)
                    mma_bf16(acc[mi][ni], al[mi], bh[ni]);
        }

        if (tt < 16) {
#pragma unroll
            for (int mi = 0; mi < 4; mi++)
#pragma unroll
                for (int h = 0; h < 2; h++) {
                    float s = 0.f;
#pragma unroll
                    for (int ni = 0; ni < 4; ni++) {
                        s += __expf(acc[mi][ni][2 * h]);
                        s += __expf(acc[mi][ni][2 * h + 1]);
                    }
                    s_run[mi][h] += s;
                }
        } else {
#pragma unroll
            for (int mi = 0; mi < 4; mi++)
#pragma unroll
                for (int h = 0; h < 2; h++) {
                    const int row = m0 + rm + mi * 16 + gq + h * 8;
                    const float inv = rowInv[mi][h];
                    __half* prow = g_p + ((size_t)b * SEQ + row) * SEQ + nt * 128;
#pragma unroll
                    for (int ni = 0; ni < 4; ni++) {
                        float p0 = __expf(acc[mi][ni][2 * h]) * inv;
                        float p1 = __expf(acc[mi][ni][2 * h + 1]) * inv;
                        *(__half2*)(prow + cn + ni * 8 + tg2) = __floats2half2_rn(p0, p1);
                    }
                }
        }

        if (tt == 15) {
#pragma unroll
            for (int mi = 0; mi < 4; mi++)
#pragma unroll
                for (int h = 0; h < 2; h++) {
                    float v = s_run[mi][h];
                    v += __shfl_xor_sync(0xffffffffu, v, 1);
                    v += __shfl_xor_sync(0xffffffffu, v, 2);
                    s_run[mi][h] = v;
                }
            if ((lane & 3) == 0) {
#pragma unroll
                for (int mi = 0; mi < 4; mi++)
#pragma unroll
                    for (int h = 0; h < 2; h++) {
                        int rl = rm + mi * 16 + gq + h * 8;
                        redS[rl * 4 + (warp >> 1)] = s_run[mi][h];
                    }
            }
            __syncthreads();
#pragma unroll
            for (int mi = 0; mi < 4; mi++)
#pragma unroll
                for (int h = 0; h < 2; h++) {
                    int rl = rm + mi * 16 + gq + h * 8;
                    float tot = redS[rl * 4] + redS[rl * 4 + 1]
                              + redS[rl * 4 + 2] + redS[rl * 4 + 3];
                    rowInv[mi][h] = 1.f / tot;
                }
        }

        __syncthreads();
        if (tt + 2 < 32) load_g(stage, (tt + 2) & 15);
        CP_COMMIT();
    }
}

// ----------------------- AV: fp16 single-term GEMM ------------------------
__global__ __launch_bounds__(THREADS, 2)
void av_gemm_kernel(const float* __restrict__ xres, float* __restrict__ out)
{
    extern __shared__ char smem[];
    const uint32_t sb = smem_u32(smem);
    const int tid = threadIdx.x;
    const int m0 = blockIdx.y * 128;
    const int n0 = blockIdx.x * 128;
    const int b  = blockIdx.z;
    const int warp = tid >> 5;
    const int lane = tid & 31;
    const int gq   = lane >> 2;
    const int tg2  = (lane & 3) * 2;
    const int rm   = (warp & 1) * 64;
    const int cn   = (warp >> 1) * 32;

    const uint32_t aoff = (uint32_t)(rm + (lane & 15)) * APITCH + (uint32_t)(lane >> 4) * 16;
    const uint32_t boff = (uint32_t)(cn + (lane & 7) + ((lane >> 4) & 1) * 8) * APITCH
                        + (uint32_t)((lane >> 3) & 1) * 16;

    const __half* Arow = g_p + (size_t)b * SEQ * SEQ + (size_t)m0 * SEQ;
    const __half* Brow = g_xt + (size_t)b * DIM * SEQ + (size_t)n0 * SEQ;
    const float* xr = xres + (size_t)b * SEQ * DIM;
    float* ob = out + (size_t)b * SEQ * DIM;

    const int r0c = tid >> 2;
    const int cc  = (tid & 3) * 16;

    float acc[4][4][4];
#pragma unroll
    for (int i = 0; i < 4; i++)
#pragma unroll
        for (int j = 0; j < 4; j++)
#pragma unroll
            for (int e = 0; e < 4; e++) acc[i][j][e] = 0.f;

    const int T = SEQ / BK;

    auto load_stage = [&](int s, int t) {
        const int k0 = t * BK;
        char* st = smem + s * AV_STAGE;
#pragma unroll
        for (int i = 0; i < 2; i++) {
            int row = r0c + i * 64;
            uint32_t doff = (uint32_t)row * APITCH + cc;
            cp16(st + doff,             (const char*)(Arow + (size_t)row * SEQ + k0) + cc);
            cp16(st + ARR_BYTES + doff, (const char*)(Brow + (size_t)row * SEQ + k0) + cc);
        }
    };

#pragma unroll
    for (int s = 0; s < AV_STAGES; s++) { load_stage(s, s); CP_COMMIT(); }

    for (int t = 0; t < T; t++) {
        CP_WAIT(AV_STAGES - 1);
        __syncthreads();
        const uint32_t stA = sb + (t % AV_STAGES) * AV_STAGE;
        const uint32_t stB = stA + ARR_BYTES;
#pragma unroll
        for (int ks = 0; ks < BK; ks += 16) {
            uint32_t a4[4][4], b4[4][2];
#pragma unroll
            for (int mi = 0; mi < 4; mi++)
                ldsm_x4(a4[mi], stA + aoff + mi * (16 * APITCH) + ks * 2);
#pragma unroll
            for (int pr = 0; pr < 2; pr++) {
                uint32_t t4[4];
                ldsm_x4(t4, stB + boff + pr * (16 * APITCH) + ks * 2);
                b4[2 * pr][0] = t4[0]; b4[2 * pr][1] = t4[1];
                b4[2 * pr + 1][0] = t4[2]; b4[2 * pr + 1][1] = t4[3];
            }
#pragma unroll
            for (int mi = 0; mi < 4; mi++)
#pragma unroll
                for (int ni = 0; ni < 4; ni++)
                    mma_f16(acc[mi][ni], a4[mi], b4[ni]);
        }
        __syncthreads();
        if (t + AV_STAGES < T) load_stage(t % AV_STAGES, t + AV_STAGES);
        CP_COMMIT();
    }

#pragma unroll
    for (int mi = 0; mi < 4; mi++)
#pragma unroll
        for (int ni = 0; ni < 4; ni++) {
            int r0 = m0 + rm + mi * 16 + gq;
            int c0 = n0 + cn + ni * 8 + tg2;
#pragma unroll
            for (int e = 0; e < 4; e++) {
                int r = r0 + (e >> 1) * 8;
                int c = c0 + (e & 1);
                ob[(size_t)r * DIM + c] = acc[mi][ni][e] + xr[(size_t)r * DIM + c];
            }
        }
}

// ------------------------------ launcher ----------------------------------
extern "C" void kernel_launch(void* const* d_in, const int* in_sizes, int n_in,
                              void* d_out, int out_size) {
    const float* x  = (const float*)d_in[0];
    const float* Wf = (const float*)d_in[1];
    const float* bf = (const float*)d_in[2];
    const float* Wg = (const float*)d_in[3];
    const float* bg = (const float*)d_in[4];
    float* out = (float*)d_out;

    cudaFuncSetAttribute(fg_gemm_kernel,
                         cudaFuncAttributeMaxDynamicSharedMemorySize, FG_SMEM);
    cudaFuncSetAttribute(fused_attn_kernel,
                         cudaFuncAttributeMaxDynamicSharedMemorySize, FUSED_SMEM);
    cudaFuncSetAttribute(av_gemm_kernel,
                         cudaFuncAttributeMaxDynamicSharedMemorySize, AV_SMEM);

    void *xh, *xl, *wth, *wtl;
    cudaGetSymbolAddress(&xh, g_xh);
    cudaGetSymbolAddress(&xl, g_xl);
    cudaGetSymbolAddress(&wth, g_wth);
    cudaGetSymbolAddress(&wtl, g_wtl);

    split_x_kernel<<<(BN_ROWS * DIM / 4) / 256, 256>>>(x, BN_ROWS * DIM / 4);
    split_w_kernel<<<(256 * DIM) / 256, 256>>>(Wf, Wg, bf, bg);
    {
        dim3 grid(SEQ / 32, DIM / 32, BATCH);
        transpose_half_kernel<<<grid, dim3(32, 8)>>>(x);
    }
    {
        dim3 grid(2, BN_ROWS / 128, 1);
        fg_gemm_kernel<<<grid, THREADS, FG_SMEM>>>(
            (const __nv_bfloat16*)xh, (const __nv_bfloat16*)xl,
            (const __nv_bfloat16*)wth, (const __nv_bfloat16*)wtl);
    }
    {
        dim3 grid(SEQ / 128, BATCH);
        fused_attn_kernel<<<grid, THREADS, FUSED_SMEM>>>();
    }
    {
        dim3 grid(DIM / 128, SEQ / 128, BATCH);
        av_gemm_kernel<<<grid, THREADS, AV_SMEM>>>(x, out);
    }
}

// round 5
// speedup vs baseline: 4.2820x; 1.0954x over previous
#include <cuda_runtime.h>
#include <cuda_bf16.h>
#include <cuda_fp16.h>
#include <cstdint>

// ---------------------------------------------------------------------------
// SelfAttention B=8 N=2048 D=1024 ATT=128
//   FG: bf16 hi/lo 3-term split GEMM (fp32-equiv), CTA 128x256, 1 wave
//   fused logits+softmax: 2-pass S-recompute, no-max softmax, P fp16
//   AV: fp16 single-term GEMM
// 512-thread CTAs everywhere (4 warps/SMSP). mma.sync + ldmatrix.x4
// (tcgen05 unavailable: harness ptxas targets sm_103 w/o 'a' features).
// ---------------------------------------------------------------------------

#define BATCH 8
#define SEQ   2048
#define DIM   1024
#define BN_ROWS (BATCH*SEQ)

#define NT 512

// pitched smem for 32-k tiles (80B = 32 elems bf16/fp16 + pad)
#define PITCH 80
#define ARR_128 (128*PITCH)            // 10240
#define ARR_256 (256*PITCH)            // 20480
// FG: A(h,l) 128 rows + B(h,l) 256 rows
#define FG_STAGE (2*ARR_128 + 2*ARR_256)   // 61440
#define FG_SMEM  (2*FG_STAGE)              // 122880
// AV: A + B, 128 rows each, fp16
#define AV_STAGE (2*ARR_128)               // 20480
#define AV_STAGES 4
#define AV_SMEM (AV_STAGES*AV_STAGE)       // 81920
// fused: pitch 272 (128 k bf16 + 16B pad)
#define FPITCH 272
#define FARR (128*FPITCH)                  // 34816
#define GOFF0 (2*FARR)
#define REDOFF (6*FARR)                    // 208896
#define FUSED_SMEM (REDOFF + 2048)

// ------------------------------- scratch ----------------------------------
__device__ __nv_bfloat16 g_xh[BN_ROWS * DIM];
__device__ __nv_bfloat16 g_xl[BN_ROWS * DIM];
__device__ __half        g_xt[(size_t)BATCH * DIM * SEQ];
__device__ __nv_bfloat16 g_wth[256 * DIM];
__device__ __nv_bfloat16 g_wtl[256 * DIM];
__device__ float         g_biasc[256];
__device__ __nv_bfloat16 g_fgh[BN_ROWS * 256];
__device__ __nv_bfloat16 g_fgl[BN_ROWS * 256];
__device__ __half        g_p[(size_t)BATCH * SEQ * SEQ];

// ------------------------------- helpers ----------------------------------
__device__ __forceinline__ uint32_t smem_u32(const void* p) {
    uint32_t a;
    asm("{ .reg .u64 t; cvta.to.shared.u64 t, %1; cvt.u32.u64 %0, t; }"
        : "=r"(a) : "l"(p));
    return a;
}
__device__ __forceinline__ void mma_bf16(float* c, const uint32_t* a, const uint32_t* b) {
    asm volatile(
        "mma.sync.aligned.m16n8k16.row.col.f32.bf16.bf16.f32 "
        "{%0,%1,%2,%3},{%4,%5,%6,%7},{%8,%9},{%0,%1,%2,%3};\n"
        : "+f"(c[0]), "+f"(c[1]), "+f"(c[2]), "+f"(c[3])
        : "r"(a[0]), "r"(a[1]), "r"(a[2]), "r"(a[3]), "r"(b[0]), "r"(b[1]));
}
__device__ __forceinline__ void mma_f16(float* c, const uint32_t* a, const uint32_t* b) {
    asm volatile(
        "mma.sync.aligned.m16n8k16.row.col.f32.f16.f16.f32 "
        "{%0,%1,%2,%3},{%4,%5,%6,%7},{%8,%9},{%0,%1,%2,%3};\n"
        : "+f"(c[0]), "+f"(c[1]), "+f"(c[2]), "+f"(c[3])
        : "r"(a[0]), "r"(a[1]), "r"(a[2]), "r"(a[3]), "r"(b[0]), "r"(b[1]));
}
__device__ __forceinline__ void ldsm_x4(uint32_t* r, uint32_t addr) {
    asm volatile("ldmatrix.sync.aligned.m8n8.x4.shared.b16 {%0,%1,%2,%3}, [%4];"
        : "=r"(r[0]), "=r"(r[1]), "=r"(r[2]), "=r"(r[3]) : "r"(addr));
}
__device__ __forceinline__ void cp16(void* dst, const void* src) {
    uint32_t d = (uint32_t)__cvta_generic_to_shared(dst);
    asm volatile("cp.async.cg.shared.global [%0], [%1], 16;" :: "r"(d), "l"(src));
}
#define CP_COMMIT() asm volatile("cp.async.commit_group;" ::: "memory")
#define CP_WAIT(n)  asm volatile("cp.async.wait_group %0;" :: "n"(n) : "memory")

__device__ __forceinline__ void split_store(float v, __nv_bfloat16* h, __nv_bfloat16* l) {
    __nv_bfloat16 hi = __float2bfloat16(v);
    *h = hi;
    *l = __float2bfloat16(v - __bfloat162float(hi));
}

// ------------------------------ prep kernels ------------------------------
// Fused: x -> xh/xl (row-major bf16 hi/lo) AND xt (transposed fp16)
__global__ void prep_x_kernel(const float* __restrict__ x) {
    __shared__ float tile[32][33];
    int b = blockIdx.z;
    int n0 = blockIdx.x * 32, d0 = blockIdx.y * 32;
    int tx = threadIdx.x, ty = threadIdx.y;   // (32,8)
    const float* xb = x + (size_t)b * SEQ * DIM;
#pragma unroll
    for (int j = 0; j < 4; j++) {
        int n = n0 + ty + 8 * j;
        float v = xb[(size_t)n * DIM + d0 + tx];
        tile[ty + 8 * j][tx] = v;
        size_t o = ((size_t)b * SEQ + n) * DIM + d0 + tx;
        split_store(v, &g_xh[o], &g_xl[o]);
    }
    __syncthreads();
    size_t base = (size_t)b * DIM * SEQ;
#pragma unroll
    for (int j = 0; j < 4; j++) {
        float v = tile[tx][ty + 8 * j];
        g_xt[base + (size_t)(d0 + ty + 8 * j) * SEQ + n0 + tx] = __float2half(v);
    }
}

__global__ void split_w_kernel(const float* __restrict__ Wf, const float* __restrict__ Wg,
                               const float* __restrict__ bfp, const float* __restrict__ bgp) {
    int idx = blockIdx.x * blockDim.x + threadIdx.x;
    if (idx < 256) g_biasc[idx] = (idx < 128) ? bfp[idx] : bgp[idx - 128];
    if (idx >= 256 * DIM) return;
    int n = idx >> 10;
    int k = idx & 1023;
    float v = (n < 128) ? Wf[(size_t)k * 128 + n] : Wg[(size_t)k * 128 + (n - 128)];
    split_store(v, &g_wth[idx], &g_wtl[idx]);
}

// --------------------- FG: bf16 split GEMM, CTA 128x256 -------------------
// C[16384,256] = x @ W^T + bias, split-stored. grid = 128 CTAs (1 wave).
__global__ __launch_bounds__(NT)
void fg_gemm_kernel(const __nv_bfloat16* __restrict__ Ah, const __nv_bfloat16* __restrict__ Al,
                    const __nv_bfloat16* __restrict__ Bh, const __nv_bfloat16* __restrict__ Bl)
{
    extern __shared__ char smem[];
    const uint32_t sb = smem_u32(smem);
    const int tid = threadIdx.x;
    const int wid = tid >> 5;
    const int lane = tid & 31;
    const int m0 = blockIdx.x * 128;
    const int gq   = lane >> 2;
    const int tg2  = (lane & 3) * 2;
    const int rm   = (wid & 1) * 64;         // 2 m-quads of 64
    const int cn   = (wid >> 1) * 32;        // 8 n-quads of 32 -> 256

    const uint32_t aoff = (uint32_t)(rm + (lane & 15)) * PITCH + (uint32_t)(lane >> 4) * 16;
    const uint32_t boff = (uint32_t)(cn + (lane & 7) + ((lane >> 4) & 1) * 8) * PITCH
                        + (uint32_t)((lane >> 3) & 1) * 16;

    const __nv_bfloat16* Arow_h = Ah + (size_t)m0 * DIM;
    const __nv_bfloat16* Arow_l = Al + (size_t)m0 * DIM;

    const int lrow = tid >> 2;               // 0..127
    const int lcc  = (tid & 3) * 16;         // 16B chunk

    float acc[4][4][4];
#pragma unroll
    for (int i = 0; i < 4; i++)
#pragma unroll
        for (int j = 0; j < 4; j++)
#pragma unroll
            for (int e = 0; e < 4; e++) acc[i][j][e] = 0.f;

    auto load_stage = [&](int s, int t) {
        const int k0 = t * 32;
        char* st = smem + s * FG_STAGE;
        uint32_t doff = (uint32_t)lrow * PITCH + lcc;
        cp16(st + doff,           (const char*)(Arow_h + (size_t)lrow * DIM + k0) + lcc);
        cp16(st + ARR_128 + doff, (const char*)(Arow_l + (size_t)lrow * DIM + k0) + lcc);
#pragma unroll
        for (int i = 0; i < 2; i++) {
            int brow = lrow + i * 128;
            uint32_t bo = (uint32_t)brow * PITCH + lcc;
            cp16(st + 2 * ARR_128 + bo,
                 (const char*)(Bh + (size_t)brow * DIM + k0) + lcc);
            cp16(st + 2 * ARR_128 + ARR_256 + bo,
                 (const char*)(Bl + (size_t)brow * DIM + k0) + lcc);
        }
    };

    load_stage(0, 0); CP_COMMIT();
    load_stage(1, 1); CP_COMMIT();

    const int T = DIM / 32;   // 32
    for (int t = 0; t < T; t++) {
        CP_WAIT(1);
        __syncthreads();
        const uint32_t stA = sb + (t & 1) * FG_STAGE;
        const uint32_t stB = stA + 2 * ARR_128;
#pragma unroll
        for (int ks = 0; ks < 32; ks += 16) {
            uint32_t ah[4][4], al[4][4], bh[4][2], bl[4][2];
#pragma unroll
            for (int mi = 0; mi < 4; mi++) {
                ldsm_x4(ah[mi], stA + aoff + mi * (16 * PITCH) + ks * 2);
                ldsm_x4(al[mi], stA + ARR_128 + aoff + mi * (16 * PITCH) + ks * 2);
            }
#pragma unroll
            for (int pr = 0; pr < 2; pr++) {
                uint32_t t4[4];
                ldsm_x4(t4, stB + boff + pr * (16 * PITCH) + ks * 2);
                bh[2 * pr][0] = t4[0]; bh[2 * pr][1] = t4[1];
                bh[2 * pr + 1][0] = t4[2]; bh[2 * pr + 1][1] = t4[3];
                ldsm_x4(t4, stB + ARR_256 + boff + pr * (16 * PITCH) + ks * 2);
                bl[2 * pr][0] = t4[0]; bl[2 * pr][1] = t4[1];
                bl[2 * pr + 1][0] = t4[2]; bl[2 * pr + 1][1] = t4[3];
            }
#pragma unroll
            for (int mi = 0; mi < 4; mi++)
#pragma unroll
                for (int ni = 0; ni < 4; ni++)
                    mma_bf16(acc[mi][ni], ah[mi], bh[ni]);
#pragma unroll
            for (int mi = 0; mi < 4; mi++)
#pragma unroll
                for (int ni = 0; ni < 4; ni++)
                    mma_bf16(acc[mi][ni], ah[mi], bl[ni]);
#pragma unroll
            for (int mi = 0; mi < 4; mi++)
#pragma unroll
                for (int ni = 0; ni < 4; ni++)
                    mma_bf16(acc[mi][ni], al[mi], bh[ni]);
        }
        __syncthreads();
        if (t + 2 < T) load_stage(t & 1, t + 2);
        CP_COMMIT();
    }

#pragma unroll
    for (int mi = 0; mi < 4; mi++)
#pragma unroll
        for (int ni = 0; ni < 4; ni++) {
            int r0 = m0 + rm + mi * 16 + gq;
            int c0 = cn + ni * 8 + tg2;
#pragma unroll
            for (int e = 0; e < 4; e++) {
                int r = r0 + (e >> 1) * 8;
                int c = c0 + (e & 1);
                float v = acc[mi][ni][e] + g_biasc[c];
                split_store(v, &g_fgh[(size_t)r * 256 + c], &g_fgl[(size_t)r * 256 + c]);
            }
        }
}

// --------------- fused logits + softmax + P(fp16), 512 thr ----------------
__global__ __launch_bounds__(NT)
void fused_attn_kernel()
{
    extern __shared__ char smem[];
    const uint32_t sb = smem_u32(smem);
    float* redS = (float*)(smem + REDOFF);

    const int tid = threadIdx.x;
    const int wid = tid >> 5;
    const int lane = tid & 31;
    const int gq   = lane >> 2;
    const int tg2  = (lane & 3) * 2;
    const int rm   = (wid & 3) * 32;      // 4 m-quads of 32
    const int cn   = (wid >> 2) * 32;     // 4 n-quads of 32
    const int m0 = blockIdx.x * 128;
    const int b  = blockIdx.y;

    const uint32_t aoff = (uint32_t)(rm + (lane & 15)) * FPITCH + (uint32_t)(lane >> 4) * 16;
    const uint32_t boff = (uint32_t)(cn + (lane & 7) + ((lane >> 4) & 1) * 8) * FPITCH
                        + (uint32_t)((lane >> 3) & 1) * 16;

    const size_t rowbase = (size_t)b * SEQ;

    // f tile: 128 rows x 128 k (hi/lo). 2048 chunks per array, 4 per thread.
#pragma unroll
    for (int i = 0; i < 4; i++) {
        int idx = tid + i * NT;
        int row = idx >> 4;
        int c = (idx & 15) * 16;
        char* dst = smem + row * FPITCH + c;
        cp16(dst,        (const char*)(g_fgh + (rowbase + m0 + row) * 256) + c);
        cp16(dst + FARR, (const char*)(g_fgl + (rowbase + m0 + row) * 256) + c);
    }
    auto load_g = [&](int s, int nt) {
        char* st = smem + GOFF0 + s * (2 * FARR);
#pragma unroll
        for (int i = 0; i < 4; i++) {
            int idx = tid + i * NT;
            int row = idx >> 4;
            int c = (idx & 15) * 16;
            char* dst = st + row * FPITCH + c;
            cp16(dst,        (const char*)(g_fgh + (rowbase + nt * 128 + row) * 256 + 128) + c);
            cp16(dst + FARR, (const char*)(g_fgl + (rowbase + nt * 128 + row) * 256 + 128) + c);
        }
    };

    load_g(0, 0);
    CP_COMMIT();
    load_g(1, 1);
    CP_COMMIT();

    float s_run[2][2] = {{0.f, 0.f}, {0.f, 0.f}};
    float rowInv[2][2];

    for (int tt = 0; tt < 32; tt++) {
        CP_WAIT(1);
        __syncthreads();
        const int stage = tt & 1;
        const int nt = tt & 15;
        const uint32_t stG = sb + GOFF0 + stage * (2 * FARR);

        float acc[2][4][4];
#pragma unroll
        for (int i = 0; i < 2; i++)
#pragma unroll
            for (int j = 0; j < 4; j++)
#pragma unroll
                for (int e = 0; e < 4; e++) acc[i][j][e] = 0.f;

#pragma unroll
        for (int ksb = 0; ksb < 8; ksb++) {
            const int ks = ksb * 16;
            uint32_t ah[2][4], al[2][4], bh[4][2], bl[4][2];
#pragma unroll
            for (int mi = 0; mi < 2; mi++) {
                ldsm_x4(ah[mi], sb + aoff + mi * (16 * FPITCH) + ks * 2);
                ldsm_x4(al[mi], sb + FARR + aoff + mi * (16 * FPITCH) + ks * 2);
            }
#pragma unroll
            for (int pr = 0; pr < 2; pr++) {
                uint32_t t4[4];
                ldsm_x4(t4, stG + boff + pr * (16 * FPITCH) + ks * 2);
                bh[2 * pr][0] = t4[0]; bh[2 * pr][1] = t4[1];
                bh[2 * pr + 1][0] = t4[2]; bh[2 * pr + 1][1] = t4[3];
                ldsm_x4(t4, stG + FARR + boff + pr * (16 * FPITCH) + ks * 2);
                bl[2 * pr][0] = t4[0]; bl[2 * pr][1] = t4[1];
                bl[2 * pr + 1][0] = t4[2]; bl[2 * pr + 1][1] = t4[3];
            }
#pragma unroll
            for (int mi = 0; mi < 2; mi++)
#pragma unroll
                for (int ni = 0; ni < 4; ni++)
                    mma_bf16(acc[mi][ni], ah[mi], bh[ni]);
#pragma unroll
            for (int mi = 0; mi < 2; mi++)
#pragma unroll
                for (int ni = 0; ni < 4; ni++)
                    mma_bf16(acc[mi][ni], ah[mi], bl[ni]);
#pragma unroll
            for (int mi = 0; mi < 2; mi++)
#pragma unroll
                for (int ni = 0; ni < 4; ni++)
                    mma_bf16(acc[mi][ni], al[mi], bh[ni]);
        }

        if (tt < 16) {
#pragma unroll
            for (int mi = 0; mi < 2; mi++)
#pragma unroll
                for (int h = 0; h < 2; h++) {
                    float s = 0.f;
#pragma unroll
                    for (int ni = 0; ni < 4; ni++) {
                        s += __expf(acc[mi][ni][2 * h]);
                        s += __expf(acc[mi][ni][2 * h + 1]);
                    }
                    s_run[mi][h] += s;
                }
        } else {
#pragma unroll
            for (int mi = 0; mi < 2; mi++)
#pragma unroll
                for (int h = 0; h < 2; h++) {
                    const int row = m0 + rm + mi * 16 + gq + h * 8;
                    const float inv = rowInv[mi][h];
                    __half* prow = g_p + ((size_t)b * SEQ + row) * SEQ + nt * 128;
#pragma unroll
                    for (int ni = 0; ni < 4; ni++) {
                        float p0 = __expf(acc[mi][ni][2 * h]) * inv;
                        float p1 = __expf(acc[mi][ni][2 * h + 1]) * inv;
                        *(__half2*)(prow + cn + ni * 8 + tg2) = __floats2half2_rn(p0, p1);
                    }
                }
        }

        if (tt == 15) {
#pragma unroll
            for (int mi = 0; mi < 2; mi++)
#pragma unroll
                for (int h = 0; h < 2; h++) {
                    float v = s_run[mi][h];
                    v += __shfl_xor_sync(0xffffffffu, v, 1);
                    v += __shfl_xor_sync(0xffffffffu, v, 2);
                    s_run[mi][h] = v;
                }
            if ((lane & 3) == 0) {
#pragma unroll
                for (int mi = 0; mi < 2; mi++)
#pragma unroll
                    for (int h = 0; h < 2; h++) {
                        int rl = rm + mi * 16 + gq + h * 8;
                        redS[rl * 4 + (wid >> 2)] = s_run[mi][h];
                    }
            }
            __syncthreads();
#pragma unroll
            for (int mi = 0; mi < 2; mi++)
#pragma unroll
                for (int h = 0; h < 2; h++) {
                    int rl = rm + mi * 16 + gq + h * 8;
                    float tot = redS[rl * 4] + redS[rl * 4 + 1]
                              + redS[rl * 4 + 2] + redS[rl * 4 + 3];
                    rowInv[mi][h] = 1.f / tot;
                }
        }

        __syncthreads();
        if (tt + 2 < 32) load_g(stage, (tt + 2) & 15);
        CP_COMMIT();
    }
}

// ----------------------- AV: fp16 single-term GEMM ------------------------
__global__ __launch_bounds__(NT)
void av_gemm_kernel(const float* __restrict__ xres, float* __restrict__ out)
{
    extern __shared__ char smem[];
    const uint32_t sb = smem_u32(smem);
    const int tid = threadIdx.x;
    const int wid = tid >> 5;
    const int lane = tid & 31;
    const int m0 = blockIdx.y * 128;
    const int n0 = blockIdx.x * 128;
    const int b  = blockIdx.z;
    const int gq   = lane >> 2;
    const int tg2  = (lane & 3) * 2;
    const int rm   = (wid & 3) * 32;
    const int cn   = (wid >> 2) * 32;

    const uint32_t aoff = (uint32_t)(rm + (lane & 15)) * PITCH + (uint32_t)(lane >> 4) * 16;
    const uint32_t boff = (uint32_t)(cn + (lane & 7) + ((lane >> 4) & 1) * 8) * PITCH
                        + (uint32_t)((lane >> 3) & 1) * 16;

    const __half* Arow = g_p + (size_t)b * SEQ * SEQ + (size_t)m0 * SEQ;
    const __half* Brow = g_xt + (size_t)b * DIM * SEQ + (size_t)n0 * SEQ;
    const float* xr = xres + (size_t)b * SEQ * DIM;
    float* ob = out + (size_t)b * SEQ * DIM;

    const int lrow = tid >> 2;
    const int lcc  = (tid & 3) * 16;

    float acc[2][4][4];
#pragma unroll
    for (int i = 0; i < 2; i++)
#pragma unroll
        for (int j = 0; j < 4; j++)
#pragma unroll
            for (int e = 0; e < 4; e++) acc[i][j][e] = 0.f;

    auto load_stage = [&](int s, int t) {
        const int k0 = t * 32;
        char* st = smem + s * AV_STAGE;
        uint32_t doff = (uint32_t)lrow * PITCH + lcc;
        cp16(st + doff,           (const char*)(Arow + (size_t)lrow * SEQ + k0) + lcc);
        cp16(st + ARR_128 + doff, (const char*)(Brow + (size_t)lrow * SEQ + k0) + lcc);
    };

#pragma unroll
    for (int s = 0; s < AV_STAGES; s++) { load_stage(s, s); CP_COMMIT(); }

    const int T = SEQ / 32;   // 64
    for (int t = 0; t < T; t++) {
        CP_WAIT(AV_STAGES - 1);
        __syncthreads();
        const uint32_t stA = sb + (t % AV_STAGES) * AV_STAGE;
        const uint32_t stB = stA + ARR_128;
#pragma unroll
        for (int ks = 0; ks < 32; ks += 16) {
            uint32_t a4[2][4], b4[4][2];
#pragma unroll
            for (int mi = 0; mi < 2; mi++)
                ldsm_x4(a4[mi], stA + aoff + mi * (16 * PITCH) + ks * 2);
#pragma unroll
            for (int pr = 0; pr < 2; pr++) {
                uint32_t t4[4];
                ldsm_x4(t4, stB + boff + pr * (16 * PITCH) + ks * 2);
                b4[2 * pr][0] = t4[0]; b4[2 * pr][1] = t4[1];
                b4[2 * pr + 1][0] = t4[2]; b4[2 * pr + 1][1] = t4[3];
            }
#pragma unroll
            for (int mi = 0; mi < 2; mi++)
#pragma unroll
                for (int ni = 0; ni < 4; ni++)
                    mma_f16(acc[mi][ni], a4[mi], b4[ni]);
        }
        __syncthreads();
        if (t + AV_STAGES < T) load_stage(t % AV_STAGES, t + AV_STAGES);
        CP_COMMIT();
    }

#pragma unroll
    for (int mi = 0; mi < 2; mi++)
#pragma unroll
        for (int ni = 0; ni < 4; ni++) {
            int r0 = m0 + rm + mi * 16 + gq;
            int c0 = n0 + cn + ni * 8 + tg2;
#pragma unroll
            for (int e = 0; e < 4; e++) {
                int r = r0 + (e >> 1) * 8;
                int c = c0 + (e & 1);
                ob[(size_t)r * DIM + c] = acc[mi][ni][e] + xr[(size_t)r * DIM + c];
            }
        }
}

// ------------------------------ launcher ----------------------------------
extern "C" void kernel_launch(void* const* d_in, const int* in_sizes, int n_in,
                              void* d_out, int out_size) {
    const float* x  = (const float*)d_in[0];
    const float* Wf = (const float*)d_in[1];
    const float* bf = (const float*)d_in[2];
    const float* Wg = (const float*)d_in[3];
    const float* bg = (const float*)d_in[4];
    float* out = (float*)d_out;

    cudaFuncSetAttribute(fg_gemm_kernel,
                         cudaFuncAttributeMaxDynamicSharedMemorySize, FG_SMEM);
    cudaFuncSetAttribute(fused_attn_kernel,
                         cudaFuncAttributeMaxDynamicSharedMemorySize, FUSED_SMEM);
    cudaFuncSetAttribute(av_gemm_kernel,
                         cudaFuncAttributeMaxDynamicSharedMemorySize, AV_SMEM);

    void *xh, *xl, *wth, *wtl;
    cudaGetSymbolAddress(&xh, g_xh);
    cudaGetSymbolAddress(&xl, g_xl);
    cudaGetSymbolAddress(&wth, g_wth);
    cudaGetSymbolAddress(&wtl, g_wtl);

    {
        dim3 grid(SEQ / 32, DIM / 32, BATCH);
        prep_x_kernel<<<grid, dim3(32, 8)>>>(x);
    }
    split_w_kernel<<<(256 * DIM) / 256, 256>>>(Wf, Wg, bf, bg);

    // FG: grid 128 (one wave)
    fg_gemm_kernel<<<BN_ROWS / 128, NT, FG_SMEM>>>(
        (const __nv_bfloat16*)xh, (const __nv_bfloat16*)xl,
        (const __nv_bfloat16*)wth, (const __nv_bfloat16*)wtl);

    // fused logits + softmax -> P fp16
    {
        dim3 grid(SEQ / 128, BATCH);
        fused_attn_kernel<<<grid, NT, FUSED_SMEM>>>();
    }

    // AV + residual
    {
        dim3 grid(DIM / 128, SEQ / 128, BATCH);
        av_gemm_kernel<<<grid, NT, AV_SMEM>>>(x, out);
    }
}